// round 4
// baseline (speedup 1.0000x reference)
#include <cuda_runtime.h>
#include <math.h>
#include <stdint.h>

// Problem constants (fixed by the seeded reference):
//   m=8, nc=1024, nt=512, dim=2, PPU=64 -> grid 129x129 per batch.
#define M_B   8
#define NC    1024
#define NT    512
#define AX    129
#define NG    (AX * AX)            // 16641
#define HALF  64
#define INV_PPU (1.0f / 64.0f)
#define X_TOTAL (M_B * NG * 2)

#define JPAD  144                  // 9 j-tiles x 16
#define KC    64                   // contexts per smem chunk
#define NCHK  16

// gemm smem: wx bufs 2 x KC*256B, then wyy bufs 2 x KC*192B
#define WXBUF   (KC * 256)                 // 16384
#define WYBUF   (KC * 192)                 // 12288
#define OFF_WY  (2 * WXBUF)                // 32768
#define SMEM_G  (OFF_WY + 2 * WYBUF)       // 57344

// Global factor tables (static __device__: no runtime allocation)
__device__ float  g_wxd[M_B * NC * 128 * 2];   // 8.4 MB, {w,w} dup pairs, i=0..127
__device__ float  g_wxe[M_B * NC];             // wx at i=128
__device__ float  g_wyy[M_B * NC * 3 * JPAD];  // 14.2 MB, [b][c][ch][j], ch={w*y0,w*y1,w}
__device__ float2 g_mid[M_B];

__device__ __forceinline__ float ex2f(float x) {
    float r; asm("ex2.approx.f32 %0, %1;" : "=f"(r) : "f"(x)); return r;
}
__device__ __forceinline__ float soft_k(float p) {
    // weight = 2^(-((d*k)^2)), k = sqrt(0.5*log2(e)) / (1e-5 + softplus(p))
    float ls = 1e-5f + log1pf(expf(p));
    return sqrtf(0.5f * 1.44269504088896341f) / ls;
}
__device__ __forceinline__ uint32_t sm32(const void* p) {
    uint32_t a;
    asm("{ .reg .u64 t; cvta.to.shared.u64 t, %1; cvt.u32.u64 %0, t; }" : "=r"(a) : "l"(p));
    return a;
}
__device__ __forceinline__ void cp16(uint32_t dst, const void* src) {
    asm volatile("cp.async.ca.shared.global [%0], [%1], 16;" :: "r"(dst), "l"(src));
}
#define FMA2(acc, a, b) \
    asm("fma.rn.f32x2 %0, %1, %2, %0;" : "+l"(acc) : "l"(a), "l"(b))

// ------------------- Kernel 1: build factor tables -------------------
__global__ void __launch_bounds__(128) fill_kernel(const float* __restrict__ xc,
                                                   const float* __restrict__ yc,
                                                   const float* __restrict__ xt,
                                                   const float* __restrict__ lsp) {
    const int b  = blockIdx.x >> 3;
    const int sl = blockIdx.x & 7;
    const int tid = threadIdx.x;
    const int w = tid >> 5, l = tid & 31;

    // redundant per-batch min/max over concat(xc, xt): 1536 points / 128 thr
    float mn0 = 1e30f, mx0 = -1e30f, mn1 = 1e30f, mx1 = -1e30f;
    for (int idx = tid; idx < NC + NT; idx += 128) {
        const float2 p = (idx < NC)
            ? *(const float2*)(xc + (size_t)(b * NC + idx) * 2)
            : *(const float2*)(xt + (size_t)(b * NT + idx - NC) * 2);
        mn0 = fminf(mn0, p.x); mx0 = fmaxf(mx0, p.x);
        mn1 = fminf(mn1, p.y); mx1 = fmaxf(mx1, p.y);
    }
    for (int o = 16; o; o >>= 1) {
        mn0 = fminf(mn0, __shfl_xor_sync(~0u, mn0, o));
        mx0 = fmaxf(mx0, __shfl_xor_sync(~0u, mx0, o));
        mn1 = fminf(mn1, __shfl_xor_sync(~0u, mn1, o));
        mx1 = fmaxf(mx1, __shfl_xor_sync(~0u, mx1, o));
    }
    __shared__ float s[4][4];
    __shared__ float2 smid;
    if (l == 0) { s[0][w] = mn0; s[1][w] = mx0; s[2][w] = mn1; s[3][w] = mx1; }
    __syncthreads();
    if (tid == 0) {
        float a = s[0][0], bb = s[1][0], c = s[2][0], d = s[3][0];
        #pragma unroll
        for (int k = 1; k < 4; k++) {
            a = fminf(a, s[0][k]); bb = fmaxf(bb, s[1][k]);
            c = fminf(c, s[2][k]); d = fmaxf(d, s[3][k]);
        }
        smid = make_float2(0.5f * (a + bb), 0.5f * (c + d));
        g_mid[b] = smid;     // benign identical-value race across slices
    }
    __syncthreads();
    const float2 mid = smid;
    const float k0 = soft_k(lsp[0]);
    const float k1 = soft_k(lsp[1]);

    // each warp: 32 contexts; lanes sweep i/j
    for (int cc = 0; cc < 32; cc++) {
        const int c = sl * 128 + w * 32 + cc;
        const float2 v  = *(const float2*)(xc + (size_t)(b * NC + c) * 2);
        const float2 yv = *(const float2*)(yc + (size_t)(b * NC + c) * 2);
        float2* wxrow = (float2*)g_wxd + (size_t)(b * NC + c) * 128;
        float*  wyrow = g_wyy + (size_t)(b * NC + c) * 3 * JPAD;

        #pragma unroll
        for (int r = 0; r < 4; r++) {
            const int i = l + 32 * r;
            const float d = (mid.x + (float)(i - HALF) * INV_PPU - v.x) * k0;
            const float wv = ex2f(-(d * d));
            wxrow[i] = make_float2(wv, wv);
        }
        if (l == 0) {
            const float d = (mid.x + (float)(128 - HALF) * INV_PPU - v.x) * k0;
            g_wxe[b * NC + c] = ex2f(-(d * d));
        }
        #pragma unroll
        for (int r = 0; r < 4; r++) {
            const int j = l + 32 * r;
            const float d = (mid.y + (float)(j - HALF) * INV_PPU - v.y) * k1;
            const float wv = ex2f(-(d * d));
            wyrow[j] = wv * yv.x; wyrow[JPAD + j] = wv * yv.y; wyrow[2 * JPAD + j] = wv;
        }
        if (l < 16) {  // j = 128..143: real value at 128, zeros beyond
            const int j = 128 + l;
            float wv = 0.0f;
            if (l == 0) {
                const float d = (mid.y + (float)(128 - HALF) * INV_PPU - v.y) * k1;
                wv = ex2f(-(d * d));
            }
            wyrow[j] = wv * yv.x; wyrow[JPAD + j] = wv * yv.y; wyrow[2 * JPAD + j] = wv;
        }
    }
}

// ------------------- Kernel 2: batched GEMM from tables -------------------
extern __shared__ char dynsm[];

__global__ void __launch_bounds__(128, 2)
gemm_kernel(float* __restrict__ out) {
    const int b = blockIdx.y;
    const int x = blockIdx.x;
    const int tid = threadIdx.x;
    const float2 mid = g_mid[b];

    if (x < 36) {
        // ---------------- main tile: i in [it*32, it*32+32), j in [jt*16, jt*16+16)
        const int it = x & 3, jt = x >> 2;
        const int jg = tid >> 5, l = tid & 31;
        const int i = it * 32 + l;
        const uint32_t smb = sm32(dynsm);

        auto stage = [&](int ch) {
            const int c0 = ch * KC;
            const int buf = ch & 1;
            const uint32_t wxd = smb + buf * WXBUF;
            const char* wxsrc = (const char*)g_wxd
                              + ((size_t)(b * NC + c0) * 128 + (size_t)it * 32) * 8;
            for (int idx = tid; idx < KC * 16; idx += 128) {
                const int c = idx >> 4, q = idx & 15;
                cp16(wxd + c * 256 + q * 16, wxsrc + (size_t)c * 1024 + q * 16);
            }
            const uint32_t wyd = smb + OFF_WY + buf * WYBUF;
            const char* wysrc = (const char*)g_wyy
                              + (size_t)(b * NC + c0) * 3 * JPAD * 4 + (size_t)jt * 64;
            for (int idx = tid; idx < KC * 12; idx += 128) {
                const int c = idx / 12, r = idx - c * 12;
                const int ch2 = r >> 2, q = r & 3;
                cp16(wyd + c * 192 + ch2 * 64 + q * 16,
                     wysrc + (size_t)c * (3 * JPAD * 4) + ch2 * (JPAD * 4) + q * 16);
            }
            asm volatile("cp.async.commit_group;" ::: "memory");
        };

        unsigned long long acc[6] = {0, 0, 0, 0, 0, 0};
        stage(0);
        for (int ch = 0; ch < NCHK; ch++) {
            if (ch + 1 < NCHK) { stage(ch + 1); asm volatile("cp.async.wait_group 1;" ::: "memory"); }
            else               { asm volatile("cp.async.wait_group 0;" ::: "memory"); }
            __syncthreads();
            uint32_t wxa = smb + (ch & 1) * WXBUF + (uint32_t)l * 8;
            uint32_t wya = smb + OFF_WY + (ch & 1) * WYBUF + (uint32_t)jg * 16;
            #pragma unroll 8
            for (int kk = 0; kk < KC; kk++) {
                unsigned long long wx, c0a, c0b, c1a, c1b, c2a, c2b;
                asm("ld.shared.u64 %0, [%1];" : "=l"(wx) : "r"(wxa));
                asm("ld.shared.v2.u64 {%0,%1}, [%2];" : "=l"(c0a), "=l"(c0b) : "r"(wya));
                asm("ld.shared.v2.u64 {%0,%1}, [%2];" : "=l"(c1a), "=l"(c1b) : "r"(wya + 64));
                asm("ld.shared.v2.u64 {%0,%1}, [%2];" : "=l"(c2a), "=l"(c2b) : "r"(wya + 128));
                FMA2(acc[0], wx, c0a); FMA2(acc[1], wx, c0b);
                FMA2(acc[2], wx, c1a); FMA2(acc[3], wx, c1b);
                FMA2(acc[4], wx, c2a); FMA2(acc[5], wx, c2b);
                wxa += 256; wya += 192;
            }
            __syncthreads();
        }

        // epilogue
        const int j0 = jt * 16 + jg * 4;
        union { unsigned long long u; float f[2]; } v;
        #pragma unroll
        for (int chn = 0; chn < 3; chn++) {
            #pragma unroll
            for (int p = 0; p < 2; p++) {
                v.u = acc[chn * 2 + p];
                #pragma unroll
                for (int e = 0; e < 2; e++) {
                    const int j = j0 + 2 * p + e;
                    if (j < AX)
                        out[(size_t)X_TOTAL + ((size_t)(b * NG) + (size_t)i * AX + j) * 3 + chn] = v.f[e];
                }
            }
        }
        const float gx = mid.x + (float)(i - HALF) * INV_PPU;
        #pragma unroll
        for (int jj = 0; jj < 4; jj++) {
            const int j = j0 + jj;
            if (j < AX) {
                float* xg = out + ((size_t)(b * NG) + (size_t)i * AX + j) * 2;
                xg[0] = gx; xg[1] = mid.y + (float)(j - HALF) * INV_PPU;
            }
        }
    } else {
        // ---------------- edge CTA: i = 128 row, all j, full K
        float* swxe = (float*)dynsm;
        const uint32_t smb = sm32(dynsm);
        for (int idx = tid; idx < 256; idx += 128)
            cp16(smb + idx * 16, (const char*)(g_wxe + b * NC) + idx * 16);
        asm volatile("cp.async.commit_group;" ::: "memory");
        asm volatile("cp.async.wait_group 0;" ::: "memory");
        __syncthreads();

        const int j = tid;                 // 0..127
        const bool last = (tid == 127);    // also handles j = 128
        float a0 = 0.f, a1 = 0.f, a2 = 0.f, e0 = 0.f, e1 = 0.f, e2 = 0.f;
        const float* wy = g_wyy + (size_t)(b * NC) * 3 * JPAD;
        #pragma unroll 4
        for (int c = 0; c < NC; c++) {
            const float wxv = swxe[c];
            const float* r = wy + (size_t)c * 3 * JPAD;
            a0 = fmaf(wxv, __ldg(r + j), a0);
            a1 = fmaf(wxv, __ldg(r + JPAD + j), a1);
            a2 = fmaf(wxv, __ldg(r + 2 * JPAD + j), a2);
            if (last) {
                e0 = fmaf(wxv, __ldg(r + 128), e0);
                e1 = fmaf(wxv, __ldg(r + JPAD + 128), e1);
                e2 = fmaf(wxv, __ldg(r + 2 * JPAD + 128), e2);
            }
        }
        const float gx = mid.x + (float)(128 - HALF) * INV_PPU;
        {
            const size_t zb = (size_t)X_TOTAL + ((size_t)(b * NG) + (size_t)128 * AX + j) * 3;
            out[zb] = a0; out[zb + 1] = a1; out[zb + 2] = a2;
            float* xg = out + ((size_t)(b * NG) + (size_t)128 * AX + j) * 2;
            xg[0] = gx; xg[1] = mid.y + (float)(j - HALF) * INV_PPU;
        }
        if (last) {
            const size_t zb = (size_t)X_TOTAL + ((size_t)(b * NG) + (size_t)128 * AX + 128) * 3;
            out[zb] = e0; out[zb + 1] = e1; out[zb + 2] = e2;
            float* xg = out + ((size_t)(b * NG) + (size_t)128 * AX + 128) * 2;
            xg[0] = gx; xg[1] = mid.y + (float)(128 - HALF) * INV_PPU;
        }
    }
}

extern "C" void kernel_launch(void* const* d_in, const int* in_sizes, int n_in,
                              void* d_out, int out_size) {
    const float* xc  = (const float*)d_in[0];
    const float* yc  = (const float*)d_in[1];
    const float* xt  = (const float*)d_in[2];
    const float* lsp = (const float*)d_in[3];
    float* out = (float*)d_out;

    cudaFuncSetAttribute(gemm_kernel, cudaFuncAttributeMaxDynamicSharedMemorySize, SMEM_G);
    fill_kernel<<<64, 128>>>(xc, yc, xt, lsp);
    gemm_kernel<<<dim3(37, M_B), 128, SMEM_G>>>(out);
}

// round 5
// speedup vs baseline: 1.5948x; 1.5948x over previous
#include <cuda_runtime.h>
#include <math.h>
#include <stdint.h>

// Problem constants (fixed by the seeded reference):
//   m=8, nc=1024, nt=512, dim=2, PPU=64 -> grid 129x129 per batch.
#define M_B   8
#define NC    1024
#define NT    512
#define AX    129
#define NG    (AX * AX)            // 16641
#define HALF  64
#define INV_PPU (1.0f / 64.0f)
#define X_TOTAL (M_B * NG * 2)

#define KC    32                   // contexts per smem chunk (per K-half)
#define NCHK  16                   // 512 / 32 chunks per half
#define WXCH  (KC * 256)           // 8192 B
#define WYCH  (KC * 192)           // 6144 B
#define OFF_WY (4 * WXCH)          // 32768
#define SMEM_G (OFF_WY + 4 * WYCH) // 57344

// GEMM-tiled global factor tables (static __device__: no runtime allocation)
__device__ float  g_wxt[M_B * 4 * NC * 64];   // 8 MB  [b][it][c][32 x {w,w}]
__device__ float  g_wxe[M_B * NC];            // wx at i=128
__device__ float  g_wyt[M_B * 9 * NC * 48];   // 14.2 MB [b][jt][c][3ch][16j]
__device__ float2 g_mid[M_B];

__device__ __forceinline__ float ex2f(float x) {
    float r; asm("ex2.approx.f32 %0, %1;" : "=f"(r) : "f"(x)); return r;
}
__device__ __forceinline__ float soft_k(float p) {
    // weight = 2^(-((d*k)^2)), k = sqrt(0.5*log2(e)) / (1e-5 + softplus(p))
    float ls = 1e-5f + log1pf(expf(p));
    return sqrtf(0.5f * 1.44269504088896341f) / ls;
}
__device__ __forceinline__ uint32_t sm32(const void* p) {
    uint32_t a;
    asm("{ .reg .u64 t; cvta.to.shared.u64 t, %1; cvt.u32.u64 %0, t; }" : "=r"(a) : "l"(p));
    return a;
}
__device__ __forceinline__ void cp16(uint32_t dst, const void* src) {
    asm volatile("cp.async.cg.shared.global [%0], [%1], 16;" :: "r"(dst), "l"(src));
}
#define FMA2(acc, a, b) \
    asm("fma.rn.f32x2 %0, %1, %2, %0;" : "+l"(acc) : "l"(a), "l"(b))
#define ADD2(acc, p) \
    asm("add.rn.f32x2 %0, %0, %1;" : "+l"(acc) : "l"(p))

// ------------------- Kernel 1: build tiled factor tables -------------------
__global__ void __launch_bounds__(256) fill_kernel(const float* __restrict__ xc,
                                                   const float* __restrict__ yc,
                                                   const float* __restrict__ xt,
                                                   const float* __restrict__ lsp) {
    const int b  = blockIdx.x >> 5;
    const int sl = blockIdx.x & 31;     // 32 contexts per CTA
    const int tid = threadIdx.x;
    const int w = tid >> 5, l = tid & 31;

    // redundant per-batch min/max over concat(xc, xt)
    float mn0 = 1e30f, mx0 = -1e30f, mn1 = 1e30f, mx1 = -1e30f;
    for (int idx = tid; idx < NC + NT; idx += 256) {
        const float2 p = (idx < NC)
            ? *(const float2*)(xc + (size_t)(b * NC + idx) * 2)
            : *(const float2*)(xt + (size_t)(b * NT + idx - NC) * 2);
        mn0 = fminf(mn0, p.x); mx0 = fmaxf(mx0, p.x);
        mn1 = fminf(mn1, p.y); mx1 = fmaxf(mx1, p.y);
    }
    for (int o = 16; o; o >>= 1) {
        mn0 = fminf(mn0, __shfl_xor_sync(~0u, mn0, o));
        mx0 = fmaxf(mx0, __shfl_xor_sync(~0u, mx0, o));
        mn1 = fminf(mn1, __shfl_xor_sync(~0u, mn1, o));
        mx1 = fmaxf(mx1, __shfl_xor_sync(~0u, mx1, o));
    }
    __shared__ float s[4][8];
    __shared__ float2 smid;
    if (l == 0) { s[0][w] = mn0; s[1][w] = mx0; s[2][w] = mn1; s[3][w] = mx1; }
    __syncthreads();
    if (tid == 0) {
        float a = s[0][0], bb = s[1][0], c = s[2][0], d = s[3][0];
        #pragma unroll
        for (int k = 1; k < 8; k++) {
            a = fminf(a, s[0][k]); bb = fmaxf(bb, s[1][k]);
            c = fminf(c, s[2][k]); d = fmaxf(d, s[3][k]);
        }
        smid = make_float2(0.5f * (a + bb), 0.5f * (c + d));
        g_mid[b] = smid;     // benign identical-value race across CTAs of same b
    }
    __syncthreads();
    const float2 mid = smid;
    const float k0 = soft_k(lsp[0]);
    const float k1 = soft_k(lsp[1]);

    const int cl  = tid >> 3;     // 0..31 local context
    const int sub = tid & 7;      // 8 threads per context
    const int c = sl * 32 + cl;
    const float2 v  = *(const float2*)(xc + (size_t)(b * NC + c) * 2);
    const float2 yv = *(const float2*)(yc + (size_t)(b * NC + c) * 2);

    // wx: i = 0..128
    for (int i = sub; i <= 128; i += 8) {
        const float d = (mid.x + (float)(i - HALF) * INV_PPU - v.x) * k0;
        const float wv = ex2f(-(d * d));
        if (i < 128) {
            float2* dst = (float2*)g_wxt
                        + ((size_t)(b * 4 + (i >> 5)) * NC + c) * 32 + (i & 31);
            *dst = make_float2(wv, wv);
        } else {
            g_wxe[b * NC + c] = wv;
        }
    }
    // wy: j = 0..143 (zeros beyond 128)
    for (int j = sub; j < 144; j += 8) {
        float wv = 0.0f;
        if (j <= 128) {
            const float d = (mid.y + (float)(j - HALF) * INV_PPU - v.y) * k1;
            wv = ex2f(-(d * d));
        }
        float* dst = g_wyt + ((size_t)(b * 9 + (j >> 4)) * NC + c) * 48 + (j & 15);
        dst[0] = wv * yv.x; dst[16] = wv * yv.y; dst[32] = wv;
    }
}

// ------------------- Kernel 2: batched GEMM from tiled tables -------------------
extern __shared__ char dynsm[];

__global__ void __launch_bounds__(256, 2)
gemm_kernel(float* __restrict__ out) {
    const int b = blockIdx.y;
    const int x = blockIdx.x;
    const int tid = threadIdx.x;
    const float2 mid = g_mid[b];
    const uint32_t smb = sm32(dynsm);

    if (x < 36) {
        // main tile: i in [it*32, +32), j in [jt*16, +16); K split across groups
        const int it = x & 3, jt = x >> 2;
        const int half = tid >> 7;          // 0: c 0..511, 1: c 512..1023
        const int t = tid & 127;
        const int jg = t >> 5, lane = t & 31;
        const int i = it * 32 + lane;

        const uint32_t wxbase = smb + half * (2 * WXCH);
        const uint32_t wybase = smb + OFF_WY + half * (2 * WYCH);
        const char* wxsrc = (const char*)g_wxt + ((size_t)(b * 4 + it) * NC + half * 512) * 256;
        const char* wysrc = (const char*)g_wyt + ((size_t)(b * 9 + jt) * NC + half * 512) * 192;

        auto stage = [&](int ch) {
            const uint32_t wxd = wxbase + (ch & 1) * WXCH;
            const char* ws = wxsrc + (size_t)ch * WXCH;
            #pragma unroll
            for (int r = 0; r < 4; r++)
                cp16(wxd + (uint32_t)(t + 128 * r) * 16, ws + (size_t)(t + 128 * r) * 16);
            const uint32_t wyd = wybase + (ch & 1) * WYCH;
            const char* ys = wysrc + (size_t)ch * WYCH;
            #pragma unroll
            for (int r = 0; r < 3; r++)
                cp16(wyd + (uint32_t)(t + 128 * r) * 16, ys + (size_t)(t + 128 * r) * 16);
            asm volatile("cp.async.commit_group;" ::: "memory");
        };

        unsigned long long acc[6] = {0, 0, 0, 0, 0, 0};
        stage(0);
        for (int ch = 0; ch < NCHK; ch++) {
            if (ch + 1 < NCHK) { stage(ch + 1); asm volatile("cp.async.wait_group 1;" ::: "memory"); }
            else               { asm volatile("cp.async.wait_group 0;" ::: "memory"); }
            if (half == 0) asm volatile("bar.sync 1, 128;" ::: "memory");
            else           asm volatile("bar.sync 2, 128;" ::: "memory");
            uint32_t wxa = wxbase + (ch & 1) * WXCH + (uint32_t)lane * 8;
            uint32_t wya = wybase + (ch & 1) * WYCH + (uint32_t)jg * 16;
            #pragma unroll
            for (int kk = 0; kk < KC; kk++) {
                unsigned long long wx, c0a, c0b, c1a, c1b, c2a, c2b;
                asm("ld.shared.u64 %0, [%1];" : "=l"(wx) : "r"(wxa));
                asm("ld.shared.v2.u64 {%0,%1}, [%2];" : "=l"(c0a), "=l"(c0b) : "r"(wya));
                asm("ld.shared.v2.u64 {%0,%1}, [%2];" : "=l"(c1a), "=l"(c1b) : "r"(wya + 64));
                asm("ld.shared.v2.u64 {%0,%1}, [%2];" : "=l"(c2a), "=l"(c2b) : "r"(wya + 128));
                FMA2(acc[0], wx, c0a); FMA2(acc[1], wx, c0b);
                FMA2(acc[2], wx, c1a); FMA2(acc[3], wx, c1b);
                FMA2(acc[4], wx, c2a); FMA2(acc[5], wx, c2b);
                wxa += 256; wya += 192;
            }
            if (half == 0) asm volatile("bar.sync 1, 128;" ::: "memory");
            else           asm volatile("bar.sync 2, 128;" ::: "memory");
        }

        __syncthreads();
        if (half == 1) {
            const uint32_t pa = smb + (uint32_t)t * 48;
            asm volatile("st.shared.v2.u64 [%0], {%1,%2};"      :: "r"(pa),      "l"(acc[0]), "l"(acc[1]) : "memory");
            asm volatile("st.shared.v2.u64 [%0], {%1,%2};"      :: "r"(pa + 16), "l"(acc[2]), "l"(acc[3]) : "memory");
            asm volatile("st.shared.v2.u64 [%0], {%1,%2};"      :: "r"(pa + 32), "l"(acc[4]), "l"(acc[5]) : "memory");
        }
        __syncthreads();

        const int j0 = jt * 16 + jg * 4;
        if (half == 0) {
            const uint32_t pa = smb + (uint32_t)t * 48;
            unsigned long long p0, p1, p2, p3, p4, p5;
            asm("ld.shared.v2.u64 {%0,%1}, [%2];" : "=l"(p0), "=l"(p1) : "r"(pa));
            asm("ld.shared.v2.u64 {%0,%1}, [%2];" : "=l"(p2), "=l"(p3) : "r"(pa + 16));
            asm("ld.shared.v2.u64 {%0,%1}, [%2];" : "=l"(p4), "=l"(p5) : "r"(pa + 32));
            ADD2(acc[0], p0); ADD2(acc[1], p1); ADD2(acc[2], p2);
            ADD2(acc[3], p3); ADD2(acc[4], p4); ADD2(acc[5], p5);
            union { unsigned long long u; float f[2]; } v;
            #pragma unroll
            for (int chn = 0; chn < 3; chn++) {
                #pragma unroll
                for (int p = 0; p < 2; p++) {
                    v.u = acc[chn * 2 + p];
                    #pragma unroll
                    for (int e = 0; e < 2; e++) {
                        const int j = j0 + 2 * p + e;
                        if (j < AX)
                            out[(size_t)X_TOTAL + ((size_t)(b * NG) + (size_t)i * AX + j) * 3 + chn] = v.f[e];
                    }
                }
            }
        } else {
            const float gx = mid.x + (float)(i - HALF) * INV_PPU;
            #pragma unroll
            for (int jj = 0; jj < 4; jj++) {
                const int j = j0 + jj;
                if (j < AX) {
                    float* xg = out + ((size_t)(b * NG) + (size_t)i * AX + j) * 2;
                    xg[0] = gx; xg[1] = mid.y + (float)(j - HALF) * INV_PPU;
                }
            }
        }
    } else {
        // ---------------- edge CTA: i = 128 row, all j ----------------
        cp16(smb + (uint32_t)tid * 16, (const char*)(g_wxe + b * NC) + (size_t)tid * 16);
        asm volatile("cp.async.commit_group;" ::: "memory");
        asm volatile("cp.async.wait_group 0;" ::: "memory");
        __syncthreads();

        const float* swxe = (const float*)dynsm;
        const int half = tid >> 7;
        const int j = tid & 127;
        const bool last = ((tid & 127) == 127);   // also handles j = 128
        const int c0 = half * 512;

        float a0 = 0.f, a1 = 0.f, a2 = 0.f, e0 = 0.f, e1 = 0.f, e2 = 0.f;
        const float* wy  = g_wyt + ((size_t)(b * 9 + (j >> 4)) * NC + c0) * 48 + (j & 15);
        const float* wyE = g_wyt + ((size_t)(b * 9 + 8) * NC + c0) * 48;   // j=128 -> jt 8, jj 0
        #pragma unroll 4
        for (int c = 0; c < 512; c++) {
            const float wxv = swxe[c0 + c];
            const float* r = wy + (size_t)c * 48;
            a0 = fmaf(wxv, __ldg(r),      a0);
            a1 = fmaf(wxv, __ldg(r + 16), a1);
            a2 = fmaf(wxv, __ldg(r + 32), a2);
            if (last) {
                const float* re = wyE + (size_t)c * 48;
                e0 = fmaf(wxv, __ldg(re),      e0);
                e1 = fmaf(wxv, __ldg(re + 16), e1);
                e2 = fmaf(wxv, __ldg(re + 32), e2);
            }
        }
        __syncthreads();
        float* part = (float*)(dynsm + 4096);
        if (half == 1) {
            part[j * 3] = a0; part[j * 3 + 1] = a1; part[j * 3 + 2] = a2;
            if (last) { part[384] = e0; part[385] = e1; part[386] = e2; }
        }
        __syncthreads();
        if (half == 0) {
            a0 += part[j * 3]; a1 += part[j * 3 + 1]; a2 += part[j * 3 + 2];
            const float gx = mid.x + (float)(128 - HALF) * INV_PPU;
            const size_t zb = (size_t)X_TOTAL + ((size_t)(b * NG) + (size_t)128 * AX + j) * 3;
            out[zb] = a0; out[zb + 1] = a1; out[zb + 2] = a2;
            float* xg = out + ((size_t)(b * NG) + (size_t)128 * AX + j) * 2;
            xg[0] = gx; xg[1] = mid.y + (float)(j - HALF) * INV_PPU;
            if (last) {
                e0 += part[384]; e1 += part[385]; e2 += part[386];
                const size_t eb = (size_t)X_TOTAL + ((size_t)(b * NG) + (size_t)128 * AX + 128) * 3;
                out[eb] = e0; out[eb + 1] = e1; out[eb + 2] = e2;
                float* xe = out + ((size_t)(b * NG) + (size_t)128 * AX + 128) * 2;
                xe[0] = gx; xe[1] = mid.y + (float)(128 - HALF) * INV_PPU;
            }
        }
    }
}

extern "C" void kernel_launch(void* const* d_in, const int* in_sizes, int n_in,
                              void* d_out, int out_size) {
    const float* xc  = (const float*)d_in[0];
    const float* yc  = (const float*)d_in[1];
    const float* xt  = (const float*)d_in[2];
    const float* lsp = (const float*)d_in[3];
    float* out = (float*)d_out;

    cudaFuncSetAttribute(gemm_kernel, cudaFuncAttributeMaxDynamicSharedMemorySize, SMEM_G);
    fill_kernel<<<256, 256>>>(xc, yc, xt, lsp);
    gemm_kernel<<<dim3(37, M_B), 256, SMEM_G>>>(out);
}

// round 6
// speedup vs baseline: 1.6263x; 1.0198x over previous
#include <cuda_runtime.h>
#include <math.h>
#include <stdint.h>

// Problem constants (fixed by the seeded reference):
//   m=8, nc=1024, nt=512, dim=2, PPU=64 -> grid 129x129 per batch.
#define M_B   8
#define NC    1024
#define NT    512
#define AX    129
#define NG    (AX * AX)            // 16641
#define HALF  64
#define INV_PPU (1.0f / 64.0f)
#define X_TOTAL (M_B * NG * 2)

#define KC    32                   // contexts per smem chunk (per K-half)
#define NCHK  16                   // 512 / 32 chunks per half
#define WXCH  (KC * 256)           // 8192 B
#define WYCH  (KC * 192)           // 6144 B
#define OFF_WY (6 * WXCH)          // 49152 (3-ring x 2 halves of wx)
#define SMEM_G (OFF_WY + 6 * WYCH) // 86016

// GEMM-tiled global factor tables (static __device__: no runtime allocation)
__device__ float  g_wxt[M_B * 4 * NC * 64];   // 8 MB  [b][it][c][32 x {w,w}]
__device__ float  g_wxe[M_B * NC];            // wx at i=128
__device__ float  g_wyt[M_B * 9 * NC * 48];   // 14.2 MB [b][jt][c][3ch][16j]
__device__ float2 g_mid[M_B];

__device__ __forceinline__ float ex2f(float x) {
    float r; asm("ex2.approx.f32 %0, %1;" : "=f"(r) : "f"(x)); return r;
}
__device__ __forceinline__ float soft_k(float p) {
    // weight = 2^(-((d*k)^2)), k = sqrt(0.5*log2(e)) / (1e-5 + softplus(p))
    float ls = 1e-5f + log1pf(expf(p));
    return sqrtf(0.5f * 1.44269504088896341f) / ls;
}
__device__ __forceinline__ uint32_t sm32(const void* p) {
    uint32_t a;
    asm("{ .reg .u64 t; cvta.to.shared.u64 t, %1; cvt.u32.u64 %0, t; }" : "=r"(a) : "l"(p));
    return a;
}
__device__ __forceinline__ void cp16(uint32_t dst, const void* src) {
    asm volatile("cp.async.cg.shared.global [%0], [%1], 16;" :: "r"(dst), "l"(src));
}
#define FMA2(acc, a, b) \
    asm("fma.rn.f32x2 %0, %1, %2, %0;" : "+l"(acc) : "l"(a), "l"(b))
#define ADD2(acc, p) \
    asm("add.rn.f32x2 %0, %0, %1;" : "+l"(acc) : "l"(p))

// One k-step with literal shared-memory offsets (no per-k pointer math).
#define KSTEP(OX, OY0, OY1, OY2) { \
    unsigned long long wx, c0a, c0b, c1a, c1b, c2a, c2b; \
    asm("ld.shared.u64 %0, [%1+" #OX "];" : "=l"(wx) : "r"(wxa)); \
    asm("ld.shared.v2.u64 {%0,%1}, [%2+" #OY0 "];" : "=l"(c0a), "=l"(c0b) : "r"(wya)); \
    asm("ld.shared.v2.u64 {%0,%1}, [%2+" #OY1 "];" : "=l"(c1a), "=l"(c1b) : "r"(wya)); \
    asm("ld.shared.v2.u64 {%0,%1}, [%2+" #OY2 "];" : "=l"(c2a), "=l"(c2b) : "r"(wya)); \
    FMA2(acc[0], wx, c0a); FMA2(acc[1], wx, c0b); \
    FMA2(acc[2], wx, c1a); FMA2(acc[3], wx, c1b); \
    FMA2(acc[4], wx, c2a); FMA2(acc[5], wx, c2b); }

// ------------------- Kernel 1: build tiled factor tables -------------------
__global__ void __launch_bounds__(256) fill_kernel(const float* __restrict__ xc,
                                                   const float* __restrict__ yc,
                                                   const float* __restrict__ xt,
                                                   const float* __restrict__ lsp) {
    const int b  = blockIdx.x >> 5;
    const int sl = blockIdx.x & 31;     // 32 contexts per CTA
    const int tid = threadIdx.x;
    const int w = tid >> 5, l = tid & 31;

    // redundant per-batch min/max over concat(xc, xt)
    float mn0 = 1e30f, mx0 = -1e30f, mn1 = 1e30f, mx1 = -1e30f;
    for (int idx = tid; idx < NC + NT; idx += 256) {
        const float2 p = (idx < NC)
            ? *(const float2*)(xc + (size_t)(b * NC + idx) * 2)
            : *(const float2*)(xt + (size_t)(b * NT + idx - NC) * 2);
        mn0 = fminf(mn0, p.x); mx0 = fmaxf(mx0, p.x);
        mn1 = fminf(mn1, p.y); mx1 = fmaxf(mx1, p.y);
    }
    for (int o = 16; o; o >>= 1) {
        mn0 = fminf(mn0, __shfl_xor_sync(~0u, mn0, o));
        mx0 = fmaxf(mx0, __shfl_xor_sync(~0u, mx0, o));
        mn1 = fminf(mn1, __shfl_xor_sync(~0u, mn1, o));
        mx1 = fmaxf(mx1, __shfl_xor_sync(~0u, mx1, o));
    }
    __shared__ float s[4][8];
    __shared__ float2 smid;
    if (l == 0) { s[0][w] = mn0; s[1][w] = mx0; s[2][w] = mn1; s[3][w] = mx1; }
    __syncthreads();
    if (tid == 0) {
        float a = s[0][0], bb = s[1][0], c = s[2][0], d = s[3][0];
        #pragma unroll
        for (int k = 1; k < 8; k++) {
            a = fminf(a, s[0][k]); bb = fmaxf(bb, s[1][k]);
            c = fminf(c, s[2][k]); d = fmaxf(d, s[3][k]);
        }
        smid = make_float2(0.5f * (a + bb), 0.5f * (c + d));
        g_mid[b] = smid;     // benign identical-value race across CTAs of same b
    }
    __syncthreads();
    const float2 mid = smid;
    const float k0 = soft_k(lsp[0]);
    const float k1 = soft_k(lsp[1]);

    const int cl  = tid >> 3;     // 0..31 local context
    const int sub = tid & 7;      // 8 threads per context
    const int c = sl * 32 + cl;
    const float2 v  = *(const float2*)(xc + (size_t)(b * NC + c) * 2);
    const float2 yv = *(const float2*)(yc + (size_t)(b * NC + c) * 2);

    // wx: i = 0..128
    for (int i = sub; i <= 128; i += 8) {
        const float d = (mid.x + (float)(i - HALF) * INV_PPU - v.x) * k0;
        const float wv = ex2f(-(d * d));
        if (i < 128) {
            float2* dst = (float2*)g_wxt
                        + ((size_t)(b * 4 + (i >> 5)) * NC + c) * 32 + (i & 31);
            *dst = make_float2(wv, wv);
        } else {
            g_wxe[b * NC + c] = wv;
        }
    }
    // wy: j = 0..143 (zeros beyond 128)
    for (int j = sub; j < 144; j += 8) {
        float wv = 0.0f;
        if (j <= 128) {
            const float d = (mid.y + (float)(j - HALF) * INV_PPU - v.y) * k1;
            wv = ex2f(-(d * d));
        }
        float* dst = g_wyt + ((size_t)(b * 9 + (j >> 4)) * NC + c) * 48 + (j & 15);
        dst[0] = wv * yv.x; dst[16] = wv * yv.y; dst[32] = wv;
    }
}

// ------------------- Kernel 2: batched GEMM from tiled tables -------------------
extern __shared__ char dynsm[];

__global__ void __launch_bounds__(256, 2)
gemm_kernel(float* __restrict__ out) {
    const int b = blockIdx.y;
    const int x = blockIdx.x;
    const int tid = threadIdx.x;
    const float2 mid = g_mid[b];
    const uint32_t smb = sm32(dynsm);

    if (x < 36) {
        // main tile: i in [it*32, +32), j in [jt*16, +16); K split across halves
        const int it = x & 3, jt = x >> 2;
        const int half = tid >> 7;          // 0: c 0..511, 1: c 512..1023
        const int t = tid & 127;
        const int jg = t >> 5, lane = t & 31;
        const int i = it * 32 + lane;

        const uint32_t wxbase = smb + half * (3 * WXCH);
        const uint32_t wybase = smb + OFF_WY + half * (3 * WYCH);
        const char* wxsrc = (const char*)g_wxt + ((size_t)(b * 4 + it) * NC + half * 512) * 256;
        const char* wysrc = (const char*)g_wyt + ((size_t)(b * 9 + jt) * NC + half * 512) * 192;

        auto stage = [&](int ch) {
            const int buf = ch % 3;
            const uint32_t wxd = wxbase + buf * WXCH;
            const char* ws = wxsrc + (size_t)ch * WXCH;
            #pragma unroll
            for (int r = 0; r < 4; r++)
                cp16(wxd + (uint32_t)(t + 128 * r) * 16, ws + (size_t)(t + 128 * r) * 16);
            const uint32_t wyd = wybase + buf * WYCH;
            const char* ys = wysrc + (size_t)ch * WYCH;
            #pragma unroll
            for (int r = 0; r < 3; r++)
                cp16(wyd + (uint32_t)(t + 128 * r) * 16, ys + (size_t)(t + 128 * r) * 16);
            asm volatile("cp.async.commit_group;" ::: "memory");
        };

        unsigned long long acc[6] = {0, 0, 0, 0, 0, 0};
        stage(0);
        stage(1);
        for (int ch = 0; ch < NCHK; ch++) {
            // wait for chunk ch's data (leave up to 1 newer group in flight)
            if (ch + 1 < NCHK) asm volatile("cp.async.wait_group 1;" ::: "memory");
            else               asm volatile("cp.async.wait_group 0;" ::: "memory");
            if (half == 0) asm volatile("bar.sync 1, 128;" ::: "memory");
            else           asm volatile("bar.sync 2, 128;" ::: "memory");
            // buffer (ch+2)%3 == (ch-1)%3 is free: everyone is past chunk ch-1
            if (ch + 2 < NCHK) stage(ch + 2);

            const int buf = ch % 3;
            const uint32_t wxa0 = wxbase + buf * WXCH + (uint32_t)lane * 8;
            const uint32_t wya0 = wybase + buf * WYCH + (uint32_t)jg * 16;
            uint32_t wxa = wxa0, wya = wya0;
            #pragma unroll
            for (int q = 0; q < KC / 4; q++) {
                KSTEP(0,   0,   64,  128)
                KSTEP(256, 192, 256, 320)
                KSTEP(512, 384, 448, 512)
                KSTEP(768, 576, 640, 704)
                wxa += 1024; wya += 768;
            }
        }

        __syncthreads();
        if (half == 1) {
            const uint32_t pa = smb + (uint32_t)t * 48;
            asm volatile("st.shared.v2.u64 [%0], {%1,%2};" :: "r"(pa),      "l"(acc[0]), "l"(acc[1]) : "memory");
            asm volatile("st.shared.v2.u64 [%0], {%1,%2};" :: "r"(pa + 16), "l"(acc[2]), "l"(acc[3]) : "memory");
            asm volatile("st.shared.v2.u64 [%0], {%1,%2};" :: "r"(pa + 32), "l"(acc[4]), "l"(acc[5]) : "memory");
        }
        __syncthreads();

        const int j0 = jt * 16 + jg * 4;
        if (half == 0) {
            const uint32_t pa = smb + (uint32_t)t * 48;
            unsigned long long p0, p1, p2, p3, p4, p5;
            asm("ld.shared.v2.u64 {%0,%1}, [%2];" : "=l"(p0), "=l"(p1) : "r"(pa));
            asm("ld.shared.v2.u64 {%0,%1}, [%2];" : "=l"(p2), "=l"(p3) : "r"(pa + 16));
            asm("ld.shared.v2.u64 {%0,%1}, [%2];" : "=l"(p4), "=l"(p5) : "r"(pa + 32));
            ADD2(acc[0], p0); ADD2(acc[1], p1); ADD2(acc[2], p2);
            ADD2(acc[3], p3); ADD2(acc[4], p4); ADD2(acc[5], p5);
            union { unsigned long long u; float f[2]; } v;
            #pragma unroll
            for (int chn = 0; chn < 3; chn++) {
                #pragma unroll
                for (int p = 0; p < 2; p++) {
                    v.u = acc[chn * 2 + p];
                    #pragma unroll
                    for (int e = 0; e < 2; e++) {
                        const int j = j0 + 2 * p + e;
                        if (j < AX)
                            out[(size_t)X_TOTAL + ((size_t)(b * NG) + (size_t)i * AX + j) * 3 + chn] = v.f[e];
                    }
                }
            }
        } else {
            const float gx = mid.x + (float)(i - HALF) * INV_PPU;
            #pragma unroll
            for (int jj = 0; jj < 4; jj++) {
                const int j = j0 + jj;
                if (j < AX) {
                    float* xg = out + ((size_t)(b * NG) + (size_t)i * AX + j) * 2;
                    xg[0] = gx; xg[1] = mid.y + (float)(j - HALF) * INV_PPU;
                }
            }
        }
    } else {
        // ---------------- edge CTA: i = 128 row, all j ----------------
        cp16(smb + (uint32_t)tid * 16, (const char*)(g_wxe + b * NC) + (size_t)tid * 16);
        asm volatile("cp.async.commit_group;" ::: "memory");
        asm volatile("cp.async.wait_group 0;" ::: "memory");
        __syncthreads();

        const float* swxe = (const float*)dynsm;
        const int half = tid >> 7;
        const int j = tid & 127;
        const bool last = ((tid & 127) == 127);   // also handles j = 128
        const int c0 = half * 512;

        float a0 = 0.f, a1 = 0.f, a2 = 0.f, e0 = 0.f, e1 = 0.f, e2 = 0.f;
        const float* wy  = g_wyt + ((size_t)(b * 9 + (j >> 4)) * NC + c0) * 48 + (j & 15);
        const float* wyE = g_wyt + ((size_t)(b * 9 + 8) * NC + c0) * 48;   // j=128 -> jt 8, jj 0
        #pragma unroll 4
        for (int c = 0; c < 512; c++) {
            const float wxv = swxe[c0 + c];
            const float* r = wy + (size_t)c * 48;
            a0 = fmaf(wxv, __ldg(r),      a0);
            a1 = fmaf(wxv, __ldg(r + 16), a1);
            a2 = fmaf(wxv, __ldg(r + 32), a2);
            if (last) {
                const float* re = wyE + (size_t)c * 48;
                e0 = fmaf(wxv, __ldg(re),      e0);
                e1 = fmaf(wxv, __ldg(re + 16), e1);
                e2 = fmaf(wxv, __ldg(re + 32), e2);
            }
        }
        __syncthreads();
        float* part = (float*)(dynsm + 4096);
        if (half == 1) {
            part[j * 3] = a0; part[j * 3 + 1] = a1; part[j * 3 + 2] = a2;
            if (last) { part[384] = e0; part[385] = e1; part[386] = e2; }
        }
        __syncthreads();
        if (half == 0) {
            a0 += part[j * 3]; a1 += part[j * 3 + 1]; a2 += part[j * 3 + 2];
            const float gx = mid.x + (float)(128 - HALF) * INV_PPU;
            const size_t zb = (size_t)X_TOTAL + ((size_t)(b * NG) + (size_t)128 * AX + j) * 3;
            out[zb] = a0; out[zb + 1] = a1; out[zb + 2] = a2;
            float* xg = out + ((size_t)(b * NG) + (size_t)128 * AX + j) * 2;
            xg[0] = gx; xg[1] = mid.y + (float)(j - HALF) * INV_PPU;
            if (last) {
                e0 += part[384]; e1 += part[385]; e2 += part[386];
                const size_t eb = (size_t)X_TOTAL + ((size_t)(b * NG) + (size_t)128 * AX + 128) * 3;
                out[eb] = e0; out[eb + 1] = e1; out[eb + 2] = e2;
                float* xe = out + ((size_t)(b * NG) + (size_t)128 * AX + 128) * 2;
                xe[0] = gx; xe[1] = mid.y + (float)(128 - HALF) * INV_PPU;
            }
        }
    }
}

extern "C" void kernel_launch(void* const* d_in, const int* in_sizes, int n_in,
                              void* d_out, int out_size) {
    const float* xc  = (const float*)d_in[0];
    const float* yc  = (const float*)d_in[1];
    const float* xt  = (const float*)d_in[2];
    const float* lsp = (const float*)d_in[3];
    float* out = (float*)d_out;

    cudaFuncSetAttribute(gemm_kernel, cudaFuncAttributeMaxDynamicSharedMemorySize, SMEM_G);
    fill_kernel<<<256, 256>>>(xc, yc, xt, lsp);
    gemm_kernel<<<dim3(37, M_B), 256, SMEM_G>>>(out);
}

// round 7
// speedup vs baseline: 1.8493x; 1.1371x over previous
#include <cuda_runtime.h>
#include <math.h>
#include <stdint.h>

// Problem constants (fixed by the seeded reference):
//   m=8, nc=1024, nt=512, dim=2, PPU=64 -> grid 129x129 per batch.
#define M_B   8
#define NC    1024
#define NT    512
#define AX    129
#define NG    (AX * AX)            // 16641
#define HALF  64
#define INV_PPU (1.0f / 64.0f)
#define X_TOTAL (M_B * NG * 2)

#define NSPLIT 8                   // K-splits per CTA (2 warps each)
#define KSPL   (NC / NSPLIT)       // 128 contexts per split
#define KC     16                  // contexts per chunk
#define NCHK   (KSPL / KC)         // 8 chunks per split

// Per-split smem: ring-2 of [wx 16c x 128i x 4B = 8192 | wy 16c x 3ch x 8j x 4B = 1536]
#define CHB    9728                // 8192 + 1536
#define SPLB   (2 * CHB)           // 19456 per split
#define SMEM_G (NSPLIT * SPLB)     // 155648

// Global factor tables (static __device__: no runtime allocation)
__device__ __align__(16) float  g_wxq[M_B * NC * 128];    // 4 MB   [b][c][i] i<128
__device__ __align__(16) float  g_wxe[M_B * NC];          // wx at i=128
__device__ __align__(16) float  g_wyt[M_B * NC * 408];    // 13.4MB [b][c][3ch][136j]
__device__ float2 g_mid[M_B];

__device__ __forceinline__ float ex2f(float x) {
    float r; asm("ex2.approx.f32 %0, %1;" : "=f"(r) : "f"(x)); return r;
}
__device__ __forceinline__ float soft_k(float p) {
    // weight = 2^(-((d*k)^2)), k = sqrt(0.5*log2(e)) / (1e-5 + softplus(p))
    float ls = 1e-5f + log1pf(expf(p));
    return sqrtf(0.5f * 1.44269504088896341f) / ls;
}
__device__ __forceinline__ uint32_t sm32(const void* p) {
    uint32_t a;
    asm("{ .reg .u64 t; cvta.to.shared.u64 t, %1; cvt.u32.u64 %0, t; }" : "=r"(a) : "l"(p));
    return a;
}
__device__ __forceinline__ void cp16(uint32_t dst, const void* src) {
    asm volatile("cp.async.cg.shared.global [%0], [%1], 16;" :: "r"(dst), "l"(src));
}
#define FMA2(acc, a, b) \
    asm("fma.rn.f32x2 %0, %1, %2, %0;" : "+l"(acc) : "l"(a), "l"(b))
#define ADD2(acc, p) \
    asm("add.rn.f32x2 %0, %0, %1;" : "+l"(acc) : "l"(p))
#define PACK2(d, w) \
    asm("mov.b64 %0, {%1, %1};" : "=l"(d) : "f"(w))

// ------------------- Kernel 1: build factor tables -------------------
__global__ void __launch_bounds__(256) fill_kernel(const float* __restrict__ xc,
                                                   const float* __restrict__ yc,
                                                   const float* __restrict__ xt,
                                                   const float* __restrict__ lsp) {
    const int b  = blockIdx.x >> 5;
    const int sl = blockIdx.x & 31;     // 32 contexts per CTA
    const int tid = threadIdx.x;
    const int w = tid >> 5, l = tid & 31;

    // redundant per-batch min/max over concat(xc, xt)
    float mn0 = 1e30f, mx0 = -1e30f, mn1 = 1e30f, mx1 = -1e30f;
    for (int idx = tid; idx < NC + NT; idx += 256) {
        const float2 p = (idx < NC)
            ? *(const float2*)(xc + (size_t)(b * NC + idx) * 2)
            : *(const float2*)(xt + (size_t)(b * NT + idx - NC) * 2);
        mn0 = fminf(mn0, p.x); mx0 = fmaxf(mx0, p.x);
        mn1 = fminf(mn1, p.y); mx1 = fmaxf(mx1, p.y);
    }
    for (int o = 16; o; o >>= 1) {
        mn0 = fminf(mn0, __shfl_xor_sync(~0u, mn0, o));
        mx0 = fmaxf(mx0, __shfl_xor_sync(~0u, mx0, o));
        mn1 = fminf(mn1, __shfl_xor_sync(~0u, mn1, o));
        mx1 = fmaxf(mx1, __shfl_xor_sync(~0u, mx1, o));
    }
    __shared__ float s[4][8];
    __shared__ float2 smid;
    if (l == 0) { s[0][w] = mn0; s[1][w] = mx0; s[2][w] = mn1; s[3][w] = mx1; }
    __syncthreads();
    if (tid == 0) {
        float a = s[0][0], bb = s[1][0], c = s[2][0], d = s[3][0];
        #pragma unroll
        for (int k = 1; k < 8; k++) {
            a = fminf(a, s[0][k]); bb = fmaxf(bb, s[1][k]);
            c = fminf(c, s[2][k]); d = fmaxf(d, s[3][k]);
        }
        smid = make_float2(0.5f * (a + bb), 0.5f * (c + d));
        g_mid[b] = smid;     // benign identical-value race across CTAs of same b
    }
    __syncthreads();
    const float2 mid = smid;
    const float k0 = soft_k(lsp[0]);
    const float k1 = soft_k(lsp[1]);

    const int cl  = tid >> 3;     // 0..31 local context
    const int sub = tid & 7;      // 8 threads per context
    const int c = sl * 32 + cl;
    const float2 v  = *(const float2*)(xc + (size_t)(b * NC + c) * 2);
    const float2 yv = *(const float2*)(yc + (size_t)(b * NC + c) * 2);

    // wx: i = 0..128
    float* wxrow = g_wxq + (size_t)(b * NC + c) * 128;
    for (int i = sub; i <= 128; i += 8) {
        const float d = (mid.x + (float)(i - HALF) * INV_PPU - v.x) * k0;
        const float wv = ex2f(-(d * d));
        if (i < 128) wxrow[i] = wv;
        else         g_wxe[b * NC + c] = wv;
    }
    // wy: j = 0..128 (x 3 channels {w*y0, w*y1, w})
    float* wyrow = g_wyt + (size_t)(b * NC + c) * 408;
    for (int j = sub; j <= 128; j += 8) {
        const float d = (mid.y + (float)(j - HALF) * INV_PPU - v.y) * k1;
        const float wv = ex2f(-(d * d));
        wyrow[j] = wv * yv.x; wyrow[136 + j] = wv * yv.y; wyrow[272 + j] = wv;
    }
}

// ------------------- Kernel 2: batched GEMM (1 CTA/SM, 8 K-split pipelines) ----
extern __shared__ char dynsm[];

__global__ void __launch_bounds__(512, 1)
gemm_kernel(float* __restrict__ out) {
    const int b = blockIdx.y;
    const int jt = blockIdx.x;        // 0..15 main, 16 = edge CTA
    const int tid = threadIdx.x;
    const float2 mid = g_mid[b];
    const uint32_t smb = sm32(dynsm);

    if (jt < 16) {
        const int w = tid >> 5, lane = tid & 31;
        const int s = w >> 1, jg = w & 1;       // split 0..7, j-group 0..1
        const int tl = tid & 63;                // thread-in-split
        const uint32_t sbase = smb + s * SPLB;

        // staging precompute (per thread, constant across chunks)
        const char* wxsrc = (const char*)g_wxq + (size_t)(b * NC + s * KSPL) * 512;
        const char* wysrc = (const char*)g_wyt + (size_t)(b * NC + s * KSPL) * 1632;
        const int itemA = tl;                 // wy item 0..63
        const int ccA = itemA / 6, rrA = itemA - ccA * 6;
        const uint32_t wyoffA = (uint32_t)(ccA * 96 + (rrA >> 1) * 32 + (rrA & 1) * 16);
        const uint32_t wysA   = (uint32_t)(ccA * 1632 + (rrA >> 1) * 544 + jt * 32 + (rrA & 1) * 16);
        const int itemB = tl + 64;            // 64..95, valid for tl < 32
        const int ccB = itemB / 6, rrB = itemB - ccB * 6;
        const uint32_t wyoffB = (uint32_t)(ccB * 96 + (rrB >> 1) * 32 + (rrB & 1) * 16);
        const uint32_t wysB   = (uint32_t)(ccB * 1632 + (rrB >> 1) * 544 + jt * 32 + (rrB & 1) * 16);

        auto stage = [&](int t) {
            const uint32_t dst = sbase + (t & 1) * CHB;
            const char* wsx = wxsrc + (size_t)t * 8192;
            #pragma unroll
            for (int r = 0; r < 8; r++)
                cp16(dst + (uint32_t)(tl + 64 * r) * 16, wsx + (size_t)(tl + 64 * r) * 16);
            const char* wsy = wysrc + (size_t)t * 26112;  // 16c * 1632
            cp16(dst + 8192 + wyoffA, wsy + wysA);
            if (tl < 32) cp16(dst + 8192 + wyoffB, wsy + wysB);
            asm volatile("cp.async.commit_group;" ::: "memory");
        };

        unsigned long long acc[24];           // [i 0..3][pair 0..1][ch 0..2]
        #pragma unroll
        for (int q = 0; q < 24; q++) acc[q] = 0;

        const int barid = s + 1;
        stage(0);
        for (int t = 0; t < NCHK; t++) {
            asm volatile("bar.sync %0, 64;" :: "r"(barid) : "memory");   // prev chunk consumed
            if (t + 1 < NCHK) {
                stage(t + 1);
                asm volatile("cp.async.wait_group 1;" ::: "memory");
            } else {
                asm volatile("cp.async.wait_group 0;" ::: "memory");
            }
            asm volatile("bar.sync %0, 64;" :: "r"(barid) : "memory");   // chunk t visible

            const uint32_t wxa = sbase + (t & 1) * CHB + (uint32_t)lane * 16;
            const uint32_t wya = sbase + (t & 1) * CHB + 8192 + (uint32_t)jg * 16;
            #pragma unroll 4
            for (int kk = 0; kk < KC; kk++) {
                float w0, w1, w2, w3;
                asm("ld.shared.v4.f32 {%0,%1,%2,%3}, [%4];"
                    : "=f"(w0), "=f"(w1), "=f"(w2), "=f"(w3) : "r"(wxa + kk * 512));
                unsigned long long d0, d1, d2, d3;
                PACK2(d0, w0); PACK2(d1, w1); PACK2(d2, w2); PACK2(d3, w3);
                unsigned long long y0a, y0b, y1a, y1b, y2a, y2b;
                asm("ld.shared.v2.u64 {%0,%1}, [%2];" : "=l"(y0a), "=l"(y0b) : "r"(wya + kk * 96));
                asm("ld.shared.v2.u64 {%0,%1}, [%2];" : "=l"(y1a), "=l"(y1b) : "r"(wya + kk * 96 + 32));
                asm("ld.shared.v2.u64 {%0,%1}, [%2];" : "=l"(y2a), "=l"(y2b) : "r"(wya + kk * 96 + 64));
                FMA2(acc[0],  d0, y0a); FMA2(acc[1],  d0, y1a); FMA2(acc[2],  d0, y2a);
                FMA2(acc[3],  d0, y0b); FMA2(acc[4],  d0, y1b); FMA2(acc[5],  d0, y2b);
                FMA2(acc[6],  d1, y0a); FMA2(acc[7],  d1, y1a); FMA2(acc[8],  d1, y2a);
                FMA2(acc[9],  d1, y0b); FMA2(acc[10], d1, y1b); FMA2(acc[11], d1, y2b);
                FMA2(acc[12], d2, y0a); FMA2(acc[13], d2, y1a); FMA2(acc[14], d2, y2a);
                FMA2(acc[15], d2, y0b); FMA2(acc[16], d2, y1b); FMA2(acc[17], d2, y2b);
                FMA2(acc[18], d3, y0a); FMA2(acc[19], d3, y1a); FMA2(acc[20], d3, y2a);
                FMA2(acc[21], d3, y0b); FMA2(acc[22], d3, y1b); FMA2(acc[23], d3, y2b);
            }
        }

        // ---- tree-combine the 8 split partials through smem ----
        auto store_accs = [&](int slot) {
            const uint32_t a = smb + (uint32_t)((slot * 64 + jg * 32 + lane) * 192);
            #pragma unroll
            for (int q = 0; q < 12; q++)
                asm volatile("st.shared.v2.u64 [%0], {%1,%2};"
                             :: "r"(a + q * 16), "l"(acc[2 * q]), "l"(acc[2 * q + 1]) : "memory");
        };
        auto add_accs = [&](int slot) {
            const uint32_t a = smb + (uint32_t)((slot * 64 + jg * 32 + lane) * 192);
            #pragma unroll
            for (int q = 0; q < 12; q++) {
                unsigned long long p0, p1;
                asm("ld.shared.v2.u64 {%0,%1}, [%2];" : "=l"(p0), "=l"(p1) : "r"(a + q * 16));
                ADD2(acc[2 * q], p0); ADD2(acc[2 * q + 1], p1);
            }
        };
        __syncthreads();
        if (s >= 4) store_accs(s - 4);
        __syncthreads();
        if (s < 4) add_accs(s);
        __syncthreads();
        if (s == 2 || s == 3) store_accs(s - 2);
        __syncthreads();
        if (s < 2) add_accs(s);
        __syncthreads();
        if (s == 1) store_accs(0);
        __syncthreads();

        if (s == 0) {
            add_accs(0);
            // write z for this thread's 4i x 4j x 3ch tile
            const int j0 = jt * 8 + jg * 4;
            union { unsigned long long u; float f[2]; } v;
            #pragma unroll
            for (int ii = 0; ii < 4; ii++) {
                const int i = 4 * lane + ii;
                const size_t rb = (size_t)X_TOTAL + ((size_t)(b * NG) + (size_t)i * AX + j0) * 3;
                #pragma unroll
                for (int p = 0; p < 2; p++) {
                    #pragma unroll
                    for (int ch = 0; ch < 3; ch++) {
                        v.u = acc[ii * 6 + p * 3 + ch];
                        out[rb + (2 * p) * 3 + ch]     = v.f[0];
                        out[rb + (2 * p + 1) * 3 + ch] = v.f[1];
                    }
                }
            }
        }
        // x_grid for CTA region (all 512 threads, 2 points each)
        #pragma unroll
        for (int r = 0; r < 2; r++) {
            const int idx = tid + 512 * r;
            const int i = idx >> 3, jj = idx & 7;
            const int j = jt * 8 + jj;
            float2* xg = (float2*)out + (size_t)(b * NG) + (size_t)i * AX + j;
            *xg = make_float2(mid.x + (float)(i - HALF) * INV_PPU,
                              mid.y + (float)(j - HALF) * INV_PPU);
        }
    } else {
        // ---------------- edge CTA: i = 128 row (all j) + j = 128 col (i<128) ----
        float* swxe  = (float*)dynsm;               // 1024 floats
        float* swyc  = (float*)(dynsm + 4096);      // 1024 x 3 (wy at j=128)
        float* part  = (float*)(dynsm + 16384);     // 257 x 3 partials
        for (int idx = tid; idx < NC; idx += 512)
            swxe[idx] = __ldg(g_wxe + b * NC + idx);
        for (int idx = tid; idx < NC * 3; idx += 512) {
            const int c = idx >> 2 == 0 ? 0 : idx / 3;  // avoid smart-alec: compute plainly below
        }
        for (int idx = tid; idx < NC * 3; idx += 512) {
            const int c = idx / 3, ch = idx - c * 3;
            swyc[c * 3 + ch] = __ldg(g_wyt + (size_t)(b * NC + c) * 408 + ch * 136 + 128);
        }
        __syncthreads();

        const int m0 = tid >> 1, kh = tid & 1;
        const int nit = (m0 == 255) ? 2 : 1;
        const float* wyg = g_wyt + (size_t)(b * NC) * 408;
        const float* xqg = g_wxq + (size_t)(b * NC) * 128;

        float res[2][3];
        for (int q = 0; q < nit; q++) {
            const int m = m0 + q;
            float a0 = 0.f, a1 = 0.f, a2 = 0.f;
            const int cb = kh * 512;
            if (m < AX) {            // row i=128, j=m
                #pragma unroll 4
                for (int c = cb; c < cb + 512; c++) {
                    const float wv = swxe[c];
                    const float* p = wyg + (size_t)c * 408 + m;
                    a0 = fmaf(wv, __ldg(p),       a0);
                    a1 = fmaf(wv, __ldg(p + 136), a1);
                    a2 = fmaf(wv, __ldg(p + 272), a2);
                }
            } else {                 // col j=128, i=m-129
                const int i = m - AX;
                #pragma unroll 4
                for (int c = cb; c < cb + 512; c++) {
                    const float wv = __ldg(xqg + (size_t)c * 128 + i);
                    a0 = fmaf(wv, swyc[c * 3],     a0);
                    a1 = fmaf(wv, swyc[c * 3 + 1], a1);
                    a2 = fmaf(wv, swyc[c * 3 + 2], a2);
                }
            }
            res[q][0] = a0; res[q][1] = a1; res[q][2] = a2;
        }
        if (kh == 1) {
            for (int q = 0; q < nit; q++) {
                const int m = m0 + q;
                part[m * 3] = res[q][0]; part[m * 3 + 1] = res[q][1]; part[m * 3 + 2] = res[q][2];
            }
        }
        __syncthreads();
        if (kh == 0) {
            for (int q = 0; q < nit; q++) {
                const int m = m0 + q;
                const float a0 = res[q][0] + part[m * 3];
                const float a1 = res[q][1] + part[m * 3 + 1];
                const float a2 = res[q][2] + part[m * 3 + 2];
                const int i = (m < AX) ? 128 : (m - AX);
                const int j = (m < AX) ? m : 128;
                const size_t zb = (size_t)X_TOTAL + ((size_t)(b * NG) + (size_t)i * AX + j) * 3;
                out[zb] = a0; out[zb + 1] = a1; out[zb + 2] = a2;
                float2* xg = (float2*)out + (size_t)(b * NG) + (size_t)i * AX + j;
                *xg = make_float2(mid.x + (float)(i - HALF) * INV_PPU,
                                  mid.y + (float)(j - HALF) * INV_PPU);
            }
        }
    }
}

extern "C" void kernel_launch(void* const* d_in, const int* in_sizes, int n_in,
                              void* d_out, int out_size) {
    const float* xc  = (const float*)d_in[0];
    const float* yc  = (const float*)d_in[1];
    const float* xt  = (const float*)d_in[2];
    const float* lsp = (const float*)d_in[3];
    float* out = (float*)d_out;

    cudaFuncSetAttribute(gemm_kernel, cudaFuncAttributeMaxDynamicSharedMemorySize, SMEM_G);
    fill_kernel<<<256, 256>>>(xc, yc, xt, lsp);
    gemm_kernel<<<dim3(17, M_B), 512, SMEM_G>>>(out);
}